// round 16
// baseline (speedup 1.0000x reference)
#include <cuda_runtime.h>
#include <cuda_bf16.h>
#include <cuda_fp16.h>

// Problem constants (fixed shapes)
#define T_TOK 2304
#define NB    2
#define CIN   256
#define C4    64
#define NS    4
#define NH    4
#define DH    64
#define HH    48
#define WW    48

// ---------------- scratch (device globals; no allocation allowed) ----------
__device__ __align__(128) float g_identity[NB * T_TOK * CIN];
__device__ __align__(128) float g_R[NS * NB * T_TOK * C4];
__device__ __align__(128) float g_O[NB * T_TOK * 4 * CIN];
#define NPAIR (NS * NB * T_TOK * (CIN / 2))
__device__ __align__(128) unsigned g_Qh[NPAIR];
__device__ __align__(128) unsigned g_Kh[NPAIR];
__device__ __align__(128) unsigned g_Vh[NPAIR];

// =================== split helpers ==================================
__device__ __forceinline__ unsigned pack2(float x, float y) {
    __nv_bfloat162 t = __floats2bfloat162_rn(x, y);
    return reinterpret_cast<unsigned&>(t);
}
__device__ __forceinline__ void split_pair(float x, float y, unsigned& h, unsigned& l) {
    float hx = __bfloat162float(__float2bfloat16_rn(x));
    float hy = __bfloat162float(__float2bfloat16_rn(y));
    h = pack2(hx, hy);
    l = pack2(x - hx, y - hy);
}
__device__ __forceinline__ unsigned pack2h(float x, float y) {
    __half2 t = __floats2half2_rn(x, y);
    return reinterpret_cast<unsigned&>(t);
}
__device__ __forceinline__ void ldsm4(uint4& r, unsigned addr) {
    asm volatile("ldmatrix.sync.aligned.m8n8.x4.shared.b16 {%0,%1,%2,%3}, [%4];"
                 : "=r"(r.x), "=r"(r.y), "=r"(r.z), "=r"(r.w) : "r"(addr));
}
__device__ __forceinline__ void ldsm4t(uint4& r, unsigned addr) {
    asm volatile("ldmatrix.sync.aligned.m8n8.x4.trans.shared.b16 {%0,%1,%2,%3}, [%4];"
                 : "=r"(r.x), "=r"(r.y), "=r"(r.z), "=r"(r.w) : "r"(addr));
}
__device__ __forceinline__ void cpasync16(unsigned dst, const void* src) {
    asm volatile("cp.async.cg.shared.global [%0], [%1], 16;" :: "r"(dst), "l"(src));
}
__device__ __forceinline__ unsigned smem_u32(const void* p) {
    return (unsigned)__cvta_generic_to_shared(p);
}
__device__ __forceinline__ float fexp2(float x) {
    float y;
    asm("ex2.approx.f32 %0, %1;" : "=f"(y) : "f"(x));
    return y;
}

#define MMA4(C, A, B0, B1)                                                    \
    asm volatile("mma.sync.aligned.m16n8k16.row.col.f32.bf16.bf16.f32 "       \
                 "{%0,%1,%2,%3}, {%4,%5,%6,%7}, {%8,%9}, {%0,%1,%2,%3};"      \
                 : "+f"(C[0]), "+f"(C[1]), "+f"(C[2]), "+f"(C[3])             \
                 : "r"(A.x), "r"(A.y), "r"(A.z), "r"(A.w), "r"(B0), "r"(B1))

#define MMA4H(C, A, B0, B1)                                                   \
    asm volatile("mma.sync.aligned.m16n8k16.row.col.f32.f16.f16.f32 "         \
                 "{%0,%1,%2,%3}, {%4,%5,%6,%7}, {%8,%9}, {%0,%1,%2,%3};"      \
                 : "+f"(C[0]), "+f"(C[1]), "+f"(C[2]), "+f"(C[3])             \
                 : "r"(A.x), "r"(A.y), "r"(A.z), "r"(A.w), "r"(B0), "r"(B1))

#define SQ 36

// ============ tensor-core split GEMM: C[M,N] = A[M,K] @ W[N,K]^T ===========
#define GEMM_SMEM (384 * SQ * 4)
__global__ void __launch_bounds__(256) gemm_mma(
    const float* __restrict__ A, const float* __restrict__ W,
    int M, int N, int K,
    float* __restrict__ Cf,
    const float* __restrict__ bng, const float* __restrict__ bnb,
    const float* __restrict__ bnm, const float* __restrict__ bnv,
    float* __restrict__ C2, int c2cols)
{
    extern __shared__ unsigned gsm[];
    unsigned* AhS = gsm;
    unsigned* AlS = gsm + 128 * SQ;
    unsigned* WhS = gsm + 256 * SQ;
    unsigned* WlS = gsm + 320 * SQ;

    const int tid = threadIdx.x, lane = tid & 31, warp = tid >> 5;
    const int m0 = blockIdx.y * 128, n0 = blockIdx.x * 64;

    const unsigned sb = smem_u32(gsm);
    const unsigned laneoff =
        (((lane & 7) + ((lane >> 3) & 1) * 8) * SQ + (lane >> 4) * 4) * 4;
    const unsigned aA = sb + (warp * 16 * SQ) * 4 + laneoff;
    const unsigned aAl = aA + 128 * SQ * 4;
    const unsigned aW = sb + (256 * SQ) * 4 + laneoff;
    const unsigned aWl = aW + 64 * SQ * 4;

    float S[8][4] = {};

    for (int k0 = 0; k0 < K; k0 += 64) {
        __syncthreads();
        {
            int row = tid >> 1, half = tid & 1;
            const float* src = A + (size_t)(m0 + row) * K + k0 + half * 32;
            unsigned* dh = AhS + row * SQ + half * 16;
            unsigned* dl = AlS + row * SQ + half * 16;
#pragma unroll
            for (int i = 0; i < 8; i++) {
                float4 v = *(const float4*)(src + i * 4);
                split_pair(v.x, v.y, dh[i * 2], dl[i * 2]);
                split_pair(v.z, v.w, dh[i * 2 + 1], dl[i * 2 + 1]);
            }
        }
        {
            int row = tid >> 2, q = tid & 3;
            const float* src = W + (size_t)(n0 + row) * K + k0 + q * 16;
            unsigned* dh = WhS + row * SQ + q * 8;
            unsigned* dl = WlS + row * SQ + q * 8;
#pragma unroll
            for (int i = 0; i < 4; i++) {
                float4 v = *(const float4*)(src + i * 4);
                split_pair(v.x, v.y, dh[i * 2], dl[i * 2]);
                split_pair(v.z, v.w, dh[i * 2 + 1], dl[i * 2 + 1]);
            }
        }
        __syncthreads();

#pragma unroll
        for (int kk = 0; kk < 4; kk++) {
            uint4 Ah, Al;
            ldsm4(Ah, aA + kk * 32);
            ldsm4(Al, aAl + kk * 32);
#pragma unroll
            for (int jp = 0; jp < 4; jp++) {
                uint4 Bh, Bl;
                ldsm4(Bh, aW + (jp * 16 * SQ) * 4 + kk * 32);
                ldsm4(Bl, aWl + (jp * 16 * SQ) * 4 + kk * 32);
                MMA4(S[2 * jp],     Ah, Bh.x, Bh.z);
                MMA4(S[2 * jp],     Ah, Bl.x, Bl.z);
                MMA4(S[2 * jp],     Al, Bh.x, Bh.z);
                MMA4(S[2 * jp + 1], Ah, Bh.y, Bh.w);
                MMA4(S[2 * jp + 1], Ah, Bl.y, Bl.w);
                MMA4(S[2 * jp + 1], Al, Bh.y, Bh.w);
            }
        }
    }

    const int fr = lane >> 2, fc = lane & 3;
    const int r0 = m0 + warp * 16 + fr;
    const int r1 = r0 + 8;
#pragma unroll
    for (int j = 0; j < 8; j++) {
        int col = n0 + j * 8 + fc * 2;
        float v0 = S[j][0], v1 = S[j][1], v2 = S[j][2], v3 = S[j][3];
        if (bng) {
            float s0 = bng[col] * rsqrtf(bnv[col] + 1e-5f);
            float s1 = bng[col + 1] * rsqrtf(bnv[col + 1] + 1e-5f);
            float b0 = bnb[col] - bnm[col] * s0;
            float b1 = bnb[col + 1] - bnm[col + 1] * s1;
            v0 = v0 * s0 + b0; v1 = v1 * s1 + b1;
            v2 = v2 * s0 + b0; v3 = v3 * s1 + b1;
        }
        *(float2*)(Cf + (size_t)r0 * N + col) = make_float2(v0, v1);
        *(float2*)(Cf + (size_t)r1 * N + col) = make_float2(v2, v3);
        if (C2 && col < c2cols) {
            *(float2*)(C2 + (size_t)r0 * c2cols + col) = make_float2(v0, v1);
            *(float2*)(C2 + (size_t)r1 * c2cols + col) = make_float2(v2, v3);
        }
    }
}

// ============ fused QKV projection (single launch, grid.z selects) =========
__global__ void __launch_bounds__(256) gemm_qkv(
    const float* __restrict__ A,
    const float* __restrict__ Wq, const float* __restrict__ Wk, const float* __restrict__ Wv,
    unsigned* __restrict__ Qh, unsigned* __restrict__ Kh, unsigned* __restrict__ Vh)
{
    extern __shared__ unsigned gsm[];
    unsigned* AhS = gsm;
    unsigned* AlS = gsm + 128 * SQ;
    unsigned* WhS = gsm + 256 * SQ;
    unsigned* WlS = gsm + 320 * SQ;

    const int tid = threadIdx.x, lane = tid & 31, warp = tid >> 5;
    const int m0 = blockIdx.y * 128, n0 = blockIdx.x * 64;
    const int z = blockIdx.z;
    const float* W = (z == 0) ? Wq : (z == 1) ? Wk : Wv;
    unsigned* Chi = (z == 0) ? Qh : (z == 1) ? Kh : Vh;
    const float mult = (z == 0) ? 1.4426950408889634f : 1.0f;
    const int K = C4, N = CIN;

    const unsigned sb = smem_u32(gsm);
    const unsigned laneoff =
        (((lane & 7) + ((lane >> 3) & 1) * 8) * SQ + (lane >> 4) * 4) * 4;
    const unsigned aA = sb + (warp * 16 * SQ) * 4 + laneoff;
    const unsigned aAl = aA + 128 * SQ * 4;
    const unsigned aW = sb + (256 * SQ) * 4 + laneoff;
    const unsigned aWl = aW + 64 * SQ * 4;

    float S[8][4] = {};

    {
        int row = tid >> 1, half = tid & 1;
        const float* src = A + (size_t)(m0 + row) * K + half * 32;
        unsigned* dh = AhS + row * SQ + half * 16;
        unsigned* dl = AlS + row * SQ + half * 16;
#pragma unroll
        for (int i = 0; i < 8; i++) {
            float4 v = *(const float4*)(src + i * 4);
            split_pair(v.x, v.y, dh[i * 2], dl[i * 2]);
            split_pair(v.z, v.w, dh[i * 2 + 1], dl[i * 2 + 1]);
        }
    }
    {
        int row = tid >> 2, q = tid & 3;
        const float* src = W + (size_t)(n0 + row) * K + q * 16;
        unsigned* dh = WhS + row * SQ + q * 8;
        unsigned* dl = WlS + row * SQ + q * 8;
#pragma unroll
        for (int i = 0; i < 4; i++) {
            float4 v = *(const float4*)(src + i * 4);
            split_pair(v.x, v.y, dh[i * 2], dl[i * 2]);
            split_pair(v.z, v.w, dh[i * 2 + 1], dl[i * 2 + 1]);
        }
    }
    __syncthreads();

#pragma unroll
    for (int kk = 0; kk < 4; kk++) {
        uint4 Ah, Al;
        ldsm4(Ah, aA + kk * 32);
        ldsm4(Al, aAl + kk * 32);
#pragma unroll
        for (int jp = 0; jp < 4; jp++) {
            uint4 Bh, Bl;
            ldsm4(Bh, aW + (jp * 16 * SQ) * 4 + kk * 32);
            ldsm4(Bl, aWl + (jp * 16 * SQ) * 4 + kk * 32);
            MMA4(S[2 * jp],     Ah, Bh.x, Bh.z);
            MMA4(S[2 * jp],     Ah, Bl.x, Bl.z);
            MMA4(S[2 * jp],     Al, Bh.x, Bh.z);
            MMA4(S[2 * jp + 1], Ah, Bh.y, Bh.w);
            MMA4(S[2 * jp + 1], Ah, Bl.y, Bl.w);
            MMA4(S[2 * jp + 1], Al, Bh.y, Bh.w);
        }
    }

    const int fr = lane >> 2, fc = lane & 3;
    const int r0 = m0 + warp * 16 + fr;
    const int r1 = r0 + 8;
#pragma unroll
    for (int j = 0; j < 8; j++) {
        int col = n0 + j * 8 + fc * 2;
        int ci = col >> 1, nw = N >> 1;
        Chi[(size_t)r0 * nw + ci] = pack2h(S[j][0] * mult, S[j][1] * mult);
        Chi[(size_t)r1 * nw + ci] = pack2h(S[j][2] * mult, S[j][3] * mult);
    }
}

// ============ fused depthwise 3x3 + pointwise 1x1 + BN2 (8-token blocks) ===
__global__ void __launch_bounds__(256) dwpw8(
    const float* __restrict__ ident, const float* __restrict__ Rprev,
    const float* __restrict__ dw, const float* __restrict__ pw,
    const float* __restrict__ bn2g, const float* __restrict__ bn2b,
    const float* __restrict__ bn2m, const float* __restrict__ bn2v,
    float* __restrict__ Rout, int s)
{
    __shared__ float Ws[64 * 65];
    __shared__ float Ds[8 * 68];
    __shared__ float wsm[C4 * 9];
    const int tid = threadIdx.x;

#pragma unroll
    for (int k = 0; k < 16; k++) {
        int idx = tid + k * 256;
        int oo = idx >> 6, cc = idx & 63;
        Ws[cc * 65 + oo] = pw[idx];
    }
    for (int i = tid; i < C4 * 9; i += 256) wsm[i] = dw[i];
    __syncthreads();

    const int lt = tid >> 5;
    const int ol = tid & 31;
    const int g = blockIdx.x * 8 + lt;
    const int b = g / T_TOK, t = g - b * T_TOK;
    const int hh = t / WW, ww = t % WW;

    {
        const float* ib = ident + (size_t)b * T_TOK * CIN + s * C4;
        const float* rb = Rprev ? (Rprev + (size_t)b * T_TOK * C4) : nullptr;
        float a0 = 0.f, a1 = 0.f;
        const int c0 = ol, c1 = ol + 32;
#pragma unroll
        for (int kh = 0; kh < 3; kh++) {
            int h2 = hh + kh - 1;
            if ((unsigned)h2 >= HH) continue;
#pragma unroll
            for (int kw = 0; kw < 3; kw++) {
                int w2 = ww + kw - 1;
                if ((unsigned)w2 >= WW) continue;
                int tt = h2 * WW + w2;
                float v0 = ib[(size_t)tt * CIN + c0];
                float v1 = ib[(size_t)tt * CIN + c1];
                if (rb) {
                    v0 += rb[(size_t)tt * C4 + c0];
                    v1 += rb[(size_t)tt * C4 + c1];
                }
                a0 += v0 * wsm[c0 * 9 + kh * 3 + kw];
                a1 += v1 * wsm[c1 * 9 + kh * 3 + kw];
            }
        }
        Ds[lt * 68 + c0] = a0;
        Ds[lt * 68 + c1] = a1;
    }
    __syncthreads();

    float acc0 = 0.f, acc1 = 0.f;
#pragma unroll 16
    for (int c = 0; c < 64; c++) {
        float d = Ds[lt * 68 + c];
        acc0 += d * Ws[c * 65 + ol];
        acc1 += d * Ws[c * 65 + ol + 32];
    }
    {
        float sc0 = bn2g[ol] * rsqrtf(bn2v[ol] + 1e-5f);
        float bi0 = bn2b[ol] - bn2m[ol] * sc0;
        float sc1 = bn2g[ol + 32] * rsqrtf(bn2v[ol + 32] + 1e-5f);
        float bi1 = bn2b[ol + 32] - bn2m[ol + 32] * sc1;
        Rout[(size_t)g * C4 + ol]      = acc0 * sc0 + bi0;
        Rout[(size_t)g * C4 + ol + 32] = acc1 * sc1 + bi1;
    }
}

// ================= pure fp16 flash attention, 128-token K tiles ============
// 8 warps, Q-tile 128, K-tile 128 (two 64-wide sub-passes reusing S regs);
// cp.async double-buffered; ONE sync pair per 128 tokens (18 iters).
// Fixed-max softmax (Q pre-scaled by log2e -> ex2); V via ldmatrix.trans.
// smem u32: Qh[0..4608), stage st at 4608+st*9216: Kh(128 rows)+0, Vh+4608
#define AT_SMEM (23040 * 4)    // 92160 B -> 2 CTAs/SM
__global__ void __launch_bounds__(256, 2) attn8(
    const unsigned* __restrict__ Qhg,
    const unsigned* __restrict__ Khg,
    const unsigned* __restrict__ Vhg,
    float* __restrict__ O)
{
    extern __shared__ unsigned smu[];
    unsigned* QhS = smu;

    const int tid = threadIdx.x, lane = tid & 31, warp = tid >> 5;
    const int y = blockIdx.y;
    const int s = y >> 3, b = (y >> 2) & 1, h = y & 3;
    const int t0 = blockIdx.x * 128;
    const size_t row0 = (size_t)(s * NB + b) * T_TOK;

    const unsigned sb = smem_u32(smu);
    const unsigned laneoff =
        (((lane & 7) + ((lane >> 3) & 1) * 8) * SQ + (lane >> 4) * 4) * 4;

    // ---- stage Q (once) ----
    {
        int row = tid >> 1, off = (tid & 1) * 16;
        const uint4* sH = (const uint4*)(Qhg + (row0 + t0 + row) * 128 + h * 32 + off);
        uint4* dH = (uint4*)(QhS + row * SQ + off);
#pragma unroll
        for (int i = 0; i < 4; i++) dH[i] = sH[i];
    }

    const int fr = lane >> 2, fc = lane & 3;
    const int qr = warp * 16 + fr;

    const unsigned aQh = sb + (warp * 16 * SQ) * 4 + laneoff;

    // stage 128 tokens of K and V: thread -> row tid>>1, half (tid&1)*16 u32
    const int srow = tid >> 1, soff = (tid & 1) * 16;
    auto issue_stage = [&](int st, int kb) {
        size_t kg = (row0 + (size_t)kb * 128 + srow) * 128 + h * 32 + soff;
        unsigned base = sb + (4608 + st * 9216 + srow * SQ + soff) * 4;
#pragma unroll
        for (int i = 0; i < 4; i++) {
            cpasync16(base + i * 16,            Khg + kg + i * 4);
            cpasync16(base + 4608 * 4 + i * 16, Vhg + kg + i * 4);
        }
    };

    float Ov[8][4] = {};
    float l0s = 0.f, l1s = 0.f;

    issue_stage(0, 0);
    asm volatile("cp.async.commit_group;");

    for (int kb = 0; kb < T_TOK / 128; kb++) {
        const int cur = kb & 1;
        if (kb + 1 < T_TOK / 128) {
            issue_stage(cur ^ 1, kb + 1);
            asm volatile("cp.async.commit_group;");
            asm volatile("cp.async.wait_group 1;");
        } else {
            asm volatile("cp.async.wait_group 0;");
        }
        __syncthreads();

        const unsigned bstg = sb + (4608 + cur * 9216) * 4 + laneoff;

#pragma unroll
        for (int hf = 0; hf < 2; hf++) {
            const unsigned aKh = bstg + (hf * 64 * SQ) * 4;
            const unsigned aVh = bstg + (4608 + hf * 64 * SQ) * 4;

            // ---- S = Qh Kh^T : 16x64 per warp ----
            float S[8][4];
#pragma unroll
            for (int j = 0; j < 8; j++)
                S[j][0] = S[j][1] = S[j][2] = S[j][3] = 0.f;

#pragma unroll
            for (int kk = 0; kk < 4; kk++) {
                uint4 Ah;
                ldsm4(Ah, aQh + kk * 32);
#pragma unroll
                for (int jp = 0; jp < 4; jp++) {
                    uint4 Bh;
                    ldsm4(Bh, aKh + (jp * 16 * SQ) * 4 + kk * 32);
                    MMA4H(S[2 * jp],     Ah, Bh.x, Bh.z);
                    MMA4H(S[2 * jp + 1], Ah, Bh.y, Bh.w);
                }
            }

            // ---- softmax (fixed max 0; ex2) + fp16 P + PV ----
#pragma unroll
            for (int kk = 0; kk < 4; kk++) {
                const int j0 = 2 * kk, j1 = 2 * kk + 1;
                float p00 = fexp2(S[j0][0]), p01 = fexp2(S[j0][1]);
                float p02 = fexp2(S[j0][2]), p03 = fexp2(S[j0][3]);
                float p10 = fexp2(S[j1][0]), p11 = fexp2(S[j1][1]);
                float p12 = fexp2(S[j1][2]), p13 = fexp2(S[j1][3]);
                l0s += (p00 + p01) + (p10 + p11);
                l1s += (p02 + p03) + (p12 + p13);
                uint4 Ph;
                Ph.x = pack2h(p00, p01);
                Ph.y = pack2h(p02, p03);
                Ph.z = pack2h(p10, p11);
                Ph.w = pack2h(p12, p13);
#pragma unroll
                for (int jp = 0; jp < 4; jp++) {
                    uint4 Bh;
                    ldsm4t(Bh, aVh + (kk * 16 * SQ) * 4 + jp * 32);
                    MMA4H(Ov[2 * jp],     Ph, Bh.x, Bh.y);
                    MMA4H(Ov[2 * jp + 1], Ph, Bh.z, Bh.w);
                }
            }
        }
        __syncthreads();
    }

    // ---- epilogue: reduce l over the quad, normalize, store ----
    l0s += __shfl_xor_sync(0xffffffffu, l0s, 1);
    l0s += __shfl_xor_sync(0xffffffffu, l0s, 2);
    l1s += __shfl_xor_sync(0xffffffffu, l1s, 1);
    l1s += __shfl_xor_sync(0xffffffffu, l1s, 2);
    float inv0 = 1.0f / l0s, inv1 = 1.0f / l1s;
    const size_t feat0 = (size_t)s * CIN + h * DH;
    const size_t r0g = (size_t)b * T_TOK + t0 + qr;
    const size_t r1g = r0g + 8;
#pragma unroll
    for (int j = 0; j < 8; j++) {
        size_t col = feat0 + j * 8 + fc * 2;
        *(float2*)(O + r0g * (4 * CIN) + col) = make_float2(Ov[j][0] * inv0, Ov[j][1] * inv0);
        *(float2*)(O + r1g * (4 * CIN) + col) = make_float2(Ov[j][2] * inv1, Ov[j][3] * inv1);
    }
}

// ---------------------------------------------------------------------------
extern "C" void kernel_launch(void* const* d_in, const int* in_sizes, int n_in,
                              void* d_out, int out_size)
{
    const float* x    = (const float*)d_in[0];
    const float* w1   = (const float*)d_in[1];
    const float* bn1g = (const float*)d_in[2];
    const float* bn1b = (const float*)d_in[3];
    const float* bn1m = (const float*)d_in[4];
    const float* bn1v = (const float*)d_in[5];
    const float* dww  = (const float*)d_in[6];
    const float* pww  = (const float*)d_in[7];
    const float* bn2g = (const float*)d_in[8];
    const float* bn2b = (const float*)d_in[9];
    const float* bn2m = (const float*)d_in[10];
    const float* bn2v = (const float*)d_in[11];
    const float* Wq   = (const float*)d_in[12];
    const float* Wk   = (const float*)d_in[13];
    const float* Wv   = (const float*)d_in[14];
    const float* Wout = (const float*)d_in[15];
    float* out = (float*)d_out;

    void* p;
    cudaGetSymbolAddress(&p, g_identity); float* ident = (float*)p;
    cudaGetSymbolAddress(&p, g_R);        float* Rp    = (float*)p;
    cudaGetSymbolAddress(&p, g_O);        float* Op    = (float*)p;
    cudaGetSymbolAddress(&p, g_Qh);  unsigned* Qh = (unsigned*)p;
    cudaGetSymbolAddress(&p, g_Kh);  unsigned* Kh = (unsigned*)p;
    cudaGetSymbolAddress(&p, g_Vh);  unsigned* Vh = (unsigned*)p;

    cudaFuncSetAttribute(gemm_mma, cudaFuncAttributeMaxDynamicSharedMemorySize, GEMM_SMEM);
    cudaFuncSetAttribute(gemm_qkv, cudaFuncAttributeMaxDynamicSharedMemorySize, GEMM_SMEM);
    cudaFuncSetAttribute(attn8, cudaFuncAttributeMaxDynamicSharedMemorySize, AT_SMEM);

    // [0] conv_in + BN1 (inline) -> identity ; channels [0,64) also into R[0]
    gemm_mma<<<dim3(4, 36), 256, GEMM_SMEM>>>(
        x, w1, NB * T_TOK, CIN, CIN, ident, bn1g, bn1b, bn1m, bn1v, Rp, C4);

    // [1..3] Res2Net scales (fused dw+pw+BN2, 8-token blocks, grid 576)
    for (int s = 1; s <= 3; s++) {
        const float* prev = (s == 1) ? nullptr : (Rp + (size_t)(s - 1) * NB * T_TOK * C4);
        dwpw8<<<(NB * T_TOK) / 8, 256>>>(
            ident, prev, dww, pww, bn2g, bn2b, bn2m, bn2v,
            Rp + (size_t)s * NB * T_TOK * C4, s);
    }

    // [4] fused Q/K/V projections -> fp16 (Q scaled by log2e)
    gemm_qkv<<<dim3(4, 144, 3), 256, GEMM_SMEM>>>(
        Rp, Wq, Wk, Wv, Qh, Kh, Vh);

    // [5] pure fp16 flash attention, 128-token K tiles
    attn8<<<dim3(T_TOK / 128, NS * NB * NH), 256, AT_SMEM>>>(
        Qh, Kh, Vh, Op);

    // [6] output projection -> d_out
    gemm_mma<<<dim3(4, 36), 256, GEMM_SMEM>>>(
        Op, Wout, NB * T_TOK, CIN, 4 * CIN, out,
        nullptr, nullptr, nullptr, nullptr, nullptr, 0);
}

// round 17
// speedup vs baseline: 1.1183x; 1.1183x over previous
#include <cuda_runtime.h>
#include <cuda_bf16.h>
#include <cuda_fp16.h>

// Problem constants (fixed shapes)
#define T_TOK 2304
#define NB    2
#define CIN   256
#define C4    64
#define NS    4
#define NH    4
#define DH    64
#define HH    48
#define WW    48

// ---------------- scratch (device globals; no allocation allowed) ----------
__device__ __align__(128) float g_identity[NB * T_TOK * CIN];
__device__ __align__(128) float g_R[NS * NB * T_TOK * C4];
__device__ __align__(128) float g_O[NB * T_TOK * 4 * CIN];
#define NPAIR (NS * NB * T_TOK * (CIN / 2))
__device__ __align__(128) unsigned g_Qh[NPAIR];
__device__ __align__(128) unsigned g_Kh[NPAIR];
__device__ __align__(128) unsigned g_Vh[NPAIR];

// =================== split helpers ==================================
__device__ __forceinline__ unsigned pack2(float x, float y) {
    __nv_bfloat162 t = __floats2bfloat162_rn(x, y);
    return reinterpret_cast<unsigned&>(t);
}
__device__ __forceinline__ void split_pair(float x, float y, unsigned& h, unsigned& l) {
    float hx = __bfloat162float(__float2bfloat16_rn(x));
    float hy = __bfloat162float(__float2bfloat16_rn(y));
    h = pack2(hx, hy);
    l = pack2(x - hx, y - hy);
}
__device__ __forceinline__ unsigned pack2h(float x, float y) {
    __half2 t = __floats2half2_rn(x, y);
    return reinterpret_cast<unsigned&>(t);
}
__device__ __forceinline__ void ldsm4(uint4& r, unsigned addr) {
    asm volatile("ldmatrix.sync.aligned.m8n8.x4.shared.b16 {%0,%1,%2,%3}, [%4];"
                 : "=r"(r.x), "=r"(r.y), "=r"(r.z), "=r"(r.w) : "r"(addr));
}
__device__ __forceinline__ void ldsm4t(uint4& r, unsigned addr) {
    asm volatile("ldmatrix.sync.aligned.m8n8.x4.trans.shared.b16 {%0,%1,%2,%3}, [%4];"
                 : "=r"(r.x), "=r"(r.y), "=r"(r.z), "=r"(r.w) : "r"(addr));
}
__device__ __forceinline__ void cpasync16(unsigned dst, const void* src) {
    asm volatile("cp.async.cg.shared.global [%0], [%1], 16;" :: "r"(dst), "l"(src));
}
__device__ __forceinline__ unsigned smem_u32(const void* p) {
    return (unsigned)__cvta_generic_to_shared(p);
}
__device__ __forceinline__ float fexp2(float x) {
    float y;
    asm("ex2.approx.f32 %0, %1;" : "=f"(y) : "f"(x));
    return y;
}

#define MMA4(C, A, B0, B1)                                                    \
    asm volatile("mma.sync.aligned.m16n8k16.row.col.f32.bf16.bf16.f32 "       \
                 "{%0,%1,%2,%3}, {%4,%5,%6,%7}, {%8,%9}, {%0,%1,%2,%3};"      \
                 : "+f"(C[0]), "+f"(C[1]), "+f"(C[2]), "+f"(C[3])             \
                 : "r"(A.x), "r"(A.y), "r"(A.z), "r"(A.w), "r"(B0), "r"(B1))

#define MMA4H(C, A, B0, B1)                                                   \
    asm volatile("mma.sync.aligned.m16n8k16.row.col.f32.f16.f16.f32 "         \
                 "{%0,%1,%2,%3}, {%4,%5,%6,%7}, {%8,%9}, {%0,%1,%2,%3};"      \
                 : "+f"(C[0]), "+f"(C[1]), "+f"(C[2]), "+f"(C[3])             \
                 : "r"(A.x), "r"(A.y), "r"(A.z), "r"(A.w), "r"(B0), "r"(B1))

#define SQ 36

// ============ tensor-core split GEMM: C[M,N] = A[M,K] @ W[N,K]^T ===========
#define GEMM_SMEM (384 * SQ * 4)
__global__ void __launch_bounds__(256) gemm_mma(
    const float* __restrict__ A, const float* __restrict__ W,
    int M, int N, int K,
    float* __restrict__ Cf,
    const float* __restrict__ bng, const float* __restrict__ bnb,
    const float* __restrict__ bnm, const float* __restrict__ bnv,
    float* __restrict__ C2, int c2cols)
{
    extern __shared__ unsigned gsm[];
    unsigned* AhS = gsm;
    unsigned* AlS = gsm + 128 * SQ;
    unsigned* WhS = gsm + 256 * SQ;
    unsigned* WlS = gsm + 320 * SQ;

    const int tid = threadIdx.x, lane = tid & 31, warp = tid >> 5;
    const int m0 = blockIdx.y * 128, n0 = blockIdx.x * 64;

    const unsigned sb = smem_u32(gsm);
    const unsigned laneoff =
        (((lane & 7) + ((lane >> 3) & 1) * 8) * SQ + (lane >> 4) * 4) * 4;
    const unsigned aA = sb + (warp * 16 * SQ) * 4 + laneoff;
    const unsigned aAl = aA + 128 * SQ * 4;
    const unsigned aW = sb + (256 * SQ) * 4 + laneoff;
    const unsigned aWl = aW + 64 * SQ * 4;

    float S[8][4] = {};

    for (int k0 = 0; k0 < K; k0 += 64) {
        __syncthreads();
        {
            int row = tid >> 1, half = tid & 1;
            const float* src = A + (size_t)(m0 + row) * K + k0 + half * 32;
            unsigned* dh = AhS + row * SQ + half * 16;
            unsigned* dl = AlS + row * SQ + half * 16;
#pragma unroll
            for (int i = 0; i < 8; i++) {
                float4 v = *(const float4*)(src + i * 4);
                split_pair(v.x, v.y, dh[i * 2], dl[i * 2]);
                split_pair(v.z, v.w, dh[i * 2 + 1], dl[i * 2 + 1]);
            }
        }
        {
            int row = tid >> 2, q = tid & 3;
            const float* src = W + (size_t)(n0 + row) * K + k0 + q * 16;
            unsigned* dh = WhS + row * SQ + q * 8;
            unsigned* dl = WlS + row * SQ + q * 8;
#pragma unroll
            for (int i = 0; i < 4; i++) {
                float4 v = *(const float4*)(src + i * 4);
                split_pair(v.x, v.y, dh[i * 2], dl[i * 2]);
                split_pair(v.z, v.w, dh[i * 2 + 1], dl[i * 2 + 1]);
            }
        }
        __syncthreads();

#pragma unroll
        for (int kk = 0; kk < 4; kk++) {
            uint4 Ah, Al;
            ldsm4(Ah, aA + kk * 32);
            ldsm4(Al, aAl + kk * 32);
#pragma unroll
            for (int jp = 0; jp < 4; jp++) {
                uint4 Bh, Bl;
                ldsm4(Bh, aW + (jp * 16 * SQ) * 4 + kk * 32);
                ldsm4(Bl, aWl + (jp * 16 * SQ) * 4 + kk * 32);
                MMA4(S[2 * jp],     Ah, Bh.x, Bh.z);
                MMA4(S[2 * jp],     Ah, Bl.x, Bl.z);
                MMA4(S[2 * jp],     Al, Bh.x, Bh.z);
                MMA4(S[2 * jp + 1], Ah, Bh.y, Bh.w);
                MMA4(S[2 * jp + 1], Ah, Bl.y, Bl.w);
                MMA4(S[2 * jp + 1], Al, Bh.y, Bh.w);
            }
        }
    }

    const int fr = lane >> 2, fc = lane & 3;
    const int r0 = m0 + warp * 16 + fr;
    const int r1 = r0 + 8;
#pragma unroll
    for (int j = 0; j < 8; j++) {
        int col = n0 + j * 8 + fc * 2;
        float v0 = S[j][0], v1 = S[j][1], v2 = S[j][2], v3 = S[j][3];
        if (bng) {
            float s0 = bng[col] * rsqrtf(bnv[col] + 1e-5f);
            float s1 = bng[col + 1] * rsqrtf(bnv[col + 1] + 1e-5f);
            float b0 = bnb[col] - bnm[col] * s0;
            float b1 = bnb[col + 1] - bnm[col + 1] * s1;
            v0 = v0 * s0 + b0; v1 = v1 * s1 + b1;
            v2 = v2 * s0 + b0; v3 = v3 * s1 + b1;
        }
        *(float2*)(Cf + (size_t)r0 * N + col) = make_float2(v0, v1);
        *(float2*)(Cf + (size_t)r1 * N + col) = make_float2(v2, v3);
        if (C2 && col < c2cols) {
            *(float2*)(C2 + (size_t)r0 * c2cols + col) = make_float2(v0, v1);
            *(float2*)(C2 + (size_t)r1 * c2cols + col) = make_float2(v2, v3);
        }
    }
}

// ============ fused QKV projection (single launch, grid.z selects) =========
__global__ void __launch_bounds__(256) gemm_qkv(
    const float* __restrict__ A,
    const float* __restrict__ Wq, const float* __restrict__ Wk, const float* __restrict__ Wv,
    unsigned* __restrict__ Qh, unsigned* __restrict__ Kh, unsigned* __restrict__ Vh)
{
    extern __shared__ unsigned gsm[];
    unsigned* AhS = gsm;
    unsigned* AlS = gsm + 128 * SQ;
    unsigned* WhS = gsm + 256 * SQ;
    unsigned* WlS = gsm + 320 * SQ;

    const int tid = threadIdx.x, lane = tid & 31, warp = tid >> 5;
    const int m0 = blockIdx.y * 128, n0 = blockIdx.x * 64;
    const int z = blockIdx.z;
    const float* W = (z == 0) ? Wq : (z == 1) ? Wk : Wv;
    unsigned* Chi = (z == 0) ? Qh : (z == 1) ? Kh : Vh;
    const float mult = (z == 0) ? 1.4426950408889634f : 1.0f;
    const int K = C4, N = CIN;

    const unsigned sb = smem_u32(gsm);
    const unsigned laneoff =
        (((lane & 7) + ((lane >> 3) & 1) * 8) * SQ + (lane >> 4) * 4) * 4;
    const unsigned aA = sb + (warp * 16 * SQ) * 4 + laneoff;
    const unsigned aAl = aA + 128 * SQ * 4;
    const unsigned aW = sb + (256 * SQ) * 4 + laneoff;
    const unsigned aWl = aW + 64 * SQ * 4;

    float S[8][4] = {};

    {
        int row = tid >> 1, half = tid & 1;
        const float* src = A + (size_t)(m0 + row) * K + half * 32;
        unsigned* dh = AhS + row * SQ + half * 16;
        unsigned* dl = AlS + row * SQ + half * 16;
#pragma unroll
        for (int i = 0; i < 8; i++) {
            float4 v = *(const float4*)(src + i * 4);
            split_pair(v.x, v.y, dh[i * 2], dl[i * 2]);
            split_pair(v.z, v.w, dh[i * 2 + 1], dl[i * 2 + 1]);
        }
    }
    {
        int row = tid >> 2, q = tid & 3;
        const float* src = W + (size_t)(n0 + row) * K + q * 16;
        unsigned* dh = WhS + row * SQ + q * 8;
        unsigned* dl = WlS + row * SQ + q * 8;
#pragma unroll
        for (int i = 0; i < 4; i++) {
            float4 v = *(const float4*)(src + i * 4);
            split_pair(v.x, v.y, dh[i * 2], dl[i * 2]);
            split_pair(v.z, v.w, dh[i * 2 + 1], dl[i * 2 + 1]);
        }
    }
    __syncthreads();

#pragma unroll
    for (int kk = 0; kk < 4; kk++) {
        uint4 Ah, Al;
        ldsm4(Ah, aA + kk * 32);
        ldsm4(Al, aAl + kk * 32);
#pragma unroll
        for (int jp = 0; jp < 4; jp++) {
            uint4 Bh, Bl;
            ldsm4(Bh, aW + (jp * 16 * SQ) * 4 + kk * 32);
            ldsm4(Bl, aWl + (jp * 16 * SQ) * 4 + kk * 32);
            MMA4(S[2 * jp],     Ah, Bh.x, Bh.z);
            MMA4(S[2 * jp],     Ah, Bl.x, Bl.z);
            MMA4(S[2 * jp],     Al, Bh.x, Bh.z);
            MMA4(S[2 * jp + 1], Ah, Bh.y, Bh.w);
            MMA4(S[2 * jp + 1], Ah, Bl.y, Bl.w);
            MMA4(S[2 * jp + 1], Al, Bh.y, Bh.w);
        }
    }

    const int fr = lane >> 2, fc = lane & 3;
    const int r0 = m0 + warp * 16 + fr;
    const int r1 = r0 + 8;
#pragma unroll
    for (int j = 0; j < 8; j++) {
        int col = n0 + j * 8 + fc * 2;
        int ci = col >> 1, nw = N >> 1;
        Chi[(size_t)r0 * nw + ci] = pack2h(S[j][0] * mult, S[j][1] * mult);
        Chi[(size_t)r1 * nw + ci] = pack2h(S[j][2] * mult, S[j][3] * mult);
    }
}

// ============ fused depthwise 3x3 + pointwise 1x1 + BN2 (8-token blocks) ===
__global__ void __launch_bounds__(256) dwpw8(
    const float* __restrict__ ident, const float* __restrict__ Rprev,
    const float* __restrict__ dw, const float* __restrict__ pw,
    const float* __restrict__ bn2g, const float* __restrict__ bn2b,
    const float* __restrict__ bn2m, const float* __restrict__ bn2v,
    float* __restrict__ Rout, int s)
{
    __shared__ float Ws[64 * 65];
    __shared__ float Ds[8 * 68];
    __shared__ float wsm[C4 * 9];
    const int tid = threadIdx.x;

#pragma unroll
    for (int k = 0; k < 16; k++) {
        int idx = tid + k * 256;
        int oo = idx >> 6, cc = idx & 63;
        Ws[cc * 65 + oo] = pw[idx];
    }
    for (int i = tid; i < C4 * 9; i += 256) wsm[i] = dw[i];
    __syncthreads();

    const int lt = tid >> 5;
    const int ol = tid & 31;
    const int g = blockIdx.x * 8 + lt;
    const int b = g / T_TOK, t = g - b * T_TOK;
    const int hh = t / WW, ww = t % WW;

    {
        const float* ib = ident + (size_t)b * T_TOK * CIN + s * C4;
        const float* rb = Rprev ? (Rprev + (size_t)b * T_TOK * C4) : nullptr;
        float a0 = 0.f, a1 = 0.f;
        const int c0 = ol, c1 = ol + 32;
#pragma unroll
        for (int kh = 0; kh < 3; kh++) {
            int h2 = hh + kh - 1;
            if ((unsigned)h2 >= HH) continue;
#pragma unroll
            for (int kw = 0; kw < 3; kw++) {
                int w2 = ww + kw - 1;
                if ((unsigned)w2 >= WW) continue;
                int tt = h2 * WW + w2;
                float v0 = ib[(size_t)tt * CIN + c0];
                float v1 = ib[(size_t)tt * CIN + c1];
                if (rb) {
                    v0 += rb[(size_t)tt * C4 + c0];
                    v1 += rb[(size_t)tt * C4 + c1];
                }
                a0 += v0 * wsm[c0 * 9 + kh * 3 + kw];
                a1 += v1 * wsm[c1 * 9 + kh * 3 + kw];
            }
        }
        Ds[lt * 68 + c0] = a0;
        Ds[lt * 68 + c1] = a1;
    }
    __syncthreads();

    float acc0 = 0.f, acc1 = 0.f;
#pragma unroll 16
    for (int c = 0; c < 64; c++) {
        float d = Ds[lt * 68 + c];
        acc0 += d * Ws[c * 65 + ol];
        acc1 += d * Ws[c * 65 + ol + 32];
    }
    {
        float sc0 = bn2g[ol] * rsqrtf(bn2v[ol] + 1e-5f);
        float bi0 = bn2b[ol] - bn2m[ol] * sc0;
        float sc1 = bn2g[ol + 32] * rsqrtf(bn2v[ol + 32] + 1e-5f);
        float bi1 = bn2b[ol + 32] - bn2m[ol + 32] * sc1;
        Rout[(size_t)g * C4 + ol]      = acc0 * sc0 + bi0;
        Rout[(size_t)g * C4 + ol + 32] = acc1 * sc1 + bi1;
    }
}

// ================= pure fp16 flash attention, 3-stage pipeline =============
// 8 warps, Q-tile 128, K-tile 64; cp.async TRIPLE-buffered (wait_group 2:
// each 18KB stage gets two compute iterations to land).
// Fixed-max softmax (Q pre-scaled by log2e -> ex2); V via ldmatrix.trans.
// smem u32: Qh[0..4608), stage st (0..2) at 4608+st*4608: Kh+0, Vh+2304
#define AT_SMEM (18432 * 4)    // 73728 B -> 2 CTAs/SM
__global__ void __launch_bounds__(256, 2) attn9(
    const unsigned* __restrict__ Qhg,
    const unsigned* __restrict__ Khg,
    const unsigned* __restrict__ Vhg,
    float* __restrict__ O)
{
    extern __shared__ unsigned smu[];
    unsigned* QhS = smu;

    const int tid = threadIdx.x, lane = tid & 31, warp = tid >> 5;
    const int y = blockIdx.y;
    const int s = y >> 3, b = (y >> 2) & 1, h = y & 3;
    const int t0 = blockIdx.x * 128;
    const size_t row0 = (size_t)(s * NB + b) * T_TOK;

    const unsigned sb = smem_u32(smu);
    const unsigned laneoff =
        (((lane & 7) + ((lane >> 3) & 1) * 8) * SQ + (lane >> 4) * 4) * 4;

    // ---- stage Q (once) ----
    {
        int row = tid >> 1, off = (tid & 1) * 16;
        const uint4* sH = (const uint4*)(Qhg + (row0 + t0 + row) * 128 + h * 32 + off);
        uint4* dH = (uint4*)(QhS + row * SQ + off);
#pragma unroll
        for (int i = 0; i < 4; i++) dH[i] = sH[i];
    }

    const int fr = lane >> 2, fc = lane & 3;
    const int qr = warp * 16 + fr;

    const unsigned aQh = sb + (warp * 16 * SQ) * 4 + laneoff;

    const int srow = tid >> 2, soff = (tid & 3) * 8;
    auto issue_stage = [&](int st, int kb) {
        size_t kg = (row0 + (size_t)kb * 64 + srow) * 128 + h * 32 + soff;
        unsigned base = sb + (4608 + st * 4608 + srow * SQ + soff) * 4;
        cpasync16(base,                 Khg + kg);
        cpasync16(base + 16,            Khg + kg + 4);
        cpasync16(base + 2304 * 4,      Vhg + kg);
        cpasync16(base + 2304 * 4 + 16, Vhg + kg + 4);
    };

    float Ov[8][4] = {};
    float l0s = 0.f, l1s = 0.f;

    const int NKB = T_TOK / 64;
    issue_stage(0, 0);
    asm volatile("cp.async.commit_group;");
    issue_stage(1, 1);
    asm volatile("cp.async.commit_group;");

    int cur = 0;
    for (int kb = 0; kb < NKB; kb++) {
        if (kb + 2 < NKB) {
            int nst = cur >= 1 ? cur - 1 : cur + 2;   // (kb+2)%3
            issue_stage(nst, kb + 2);
            asm volatile("cp.async.commit_group;");
            asm volatile("cp.async.wait_group 2;");
        } else if (kb + 1 < NKB) {
            asm volatile("cp.async.wait_group 1;");
        } else {
            asm volatile("cp.async.wait_group 0;");
        }
        __syncthreads();

        const unsigned bstg = sb + (4608 + cur * 4608) * 4 + laneoff;
        const unsigned aKh = bstg;
        const unsigned aVh = bstg + 2304 * 4;

        // ---- S = Qh Kh^T : 16x64 per warp ----
        float S[8][4];
#pragma unroll
        for (int j = 0; j < 8; j++)
            S[j][0] = S[j][1] = S[j][2] = S[j][3] = 0.f;

#pragma unroll
        for (int kk = 0; kk < 4; kk++) {
            uint4 Ah;
            ldsm4(Ah, aQh + kk * 32);
#pragma unroll
            for (int jp = 0; jp < 4; jp++) {
                uint4 Bh;
                ldsm4(Bh, aKh + (jp * 16 * SQ) * 4 + kk * 32);
                MMA4H(S[2 * jp],     Ah, Bh.x, Bh.z);
                MMA4H(S[2 * jp + 1], Ah, Bh.y, Bh.w);
            }
        }

        // ---- softmax (fixed max 0; ex2) + fp16 P + PV ----
#pragma unroll
        for (int kk = 0; kk < 4; kk++) {
            const int j0 = 2 * kk, j1 = 2 * kk + 1;
            float p00 = fexp2(S[j0][0]), p01 = fexp2(S[j0][1]);
            float p02 = fexp2(S[j0][2]), p03 = fexp2(S[j0][3]);
            float p10 = fexp2(S[j1][0]), p11 = fexp2(S[j1][1]);
            float p12 = fexp2(S[j1][2]), p13 = fexp2(S[j1][3]);
            l0s += (p00 + p01) + (p10 + p11);
            l1s += (p02 + p03) + (p12 + p13);
            uint4 Ph;
            Ph.x = pack2h(p00, p01);
            Ph.y = pack2h(p02, p03);
            Ph.z = pack2h(p10, p11);
            Ph.w = pack2h(p12, p13);
#pragma unroll
            for (int jp = 0; jp < 4; jp++) {
                uint4 Bh;
                ldsm4t(Bh, aVh + (kk * 16 * SQ) * 4 + jp * 32);
                MMA4H(Ov[2 * jp],     Ph, Bh.x, Bh.y);
                MMA4H(Ov[2 * jp + 1], Ph, Bh.z, Bh.w);
            }
        }
        __syncthreads();
        cur = (cur < 2) ? cur + 1 : 0;
    }

    // ---- epilogue: reduce l over the quad, normalize, store ----
    l0s += __shfl_xor_sync(0xffffffffu, l0s, 1);
    l0s += __shfl_xor_sync(0xffffffffu, l0s, 2);
    l1s += __shfl_xor_sync(0xffffffffu, l1s, 1);
    l1s += __shfl_xor_sync(0xffffffffu, l1s, 2);
    float inv0 = 1.0f / l0s, inv1 = 1.0f / l1s;
    const size_t feat0 = (size_t)s * CIN + h * DH;
    const size_t r0g = (size_t)b * T_TOK + t0 + qr;
    const size_t r1g = r0g + 8;
#pragma unroll
    for (int j = 0; j < 8; j++) {
        size_t col = feat0 + j * 8 + fc * 2;
        *(float2*)(O + r0g * (4 * CIN) + col) = make_float2(Ov[j][0] * inv0, Ov[j][1] * inv0);
        *(float2*)(O + r1g * (4 * CIN) + col) = make_float2(Ov[j][2] * inv1, Ov[j][3] * inv1);
    }
}

// ---------------------------------------------------------------------------
extern "C" void kernel_launch(void* const* d_in, const int* in_sizes, int n_in,
                              void* d_out, int out_size)
{
    const float* x    = (const float*)d_in[0];
    const float* w1   = (const float*)d_in[1];
    const float* bn1g = (const float*)d_in[2];
    const float* bn1b = (const float*)d_in[3];
    const float* bn1m = (const float*)d_in[4];
    const float* bn1v = (const float*)d_in[5];
    const float* dww  = (const float*)d_in[6];
    const float* pww  = (const float*)d_in[7];
    const float* bn2g = (const float*)d_in[8];
    const float* bn2b = (const float*)d_in[9];
    const float* bn2m = (const float*)d_in[10];
    const float* bn2v = (const float*)d_in[11];
    const float* Wq   = (const float*)d_in[12];
    const float* Wk   = (const float*)d_in[13];
    const float* Wv   = (const float*)d_in[14];
    const float* Wout = (const float*)d_in[15];
    float* out = (float*)d_out;

    void* p;
    cudaGetSymbolAddress(&p, g_identity); float* ident = (float*)p;
    cudaGetSymbolAddress(&p, g_R);        float* Rp    = (float*)p;
    cudaGetSymbolAddress(&p, g_O);        float* Op    = (float*)p;
    cudaGetSymbolAddress(&p, g_Qh);  unsigned* Qh = (unsigned*)p;
    cudaGetSymbolAddress(&p, g_Kh);  unsigned* Kh = (unsigned*)p;
    cudaGetSymbolAddress(&p, g_Vh);  unsigned* Vh = (unsigned*)p;

    cudaFuncSetAttribute(gemm_mma, cudaFuncAttributeMaxDynamicSharedMemorySize, GEMM_SMEM);
    cudaFuncSetAttribute(gemm_qkv, cudaFuncAttributeMaxDynamicSharedMemorySize, GEMM_SMEM);
    cudaFuncSetAttribute(attn9, cudaFuncAttributeMaxDynamicSharedMemorySize, AT_SMEM);

    // [0] conv_in + BN1 (inline) -> identity ; channels [0,64) also into R[0]
    gemm_mma<<<dim3(4, 36), 256, GEMM_SMEM>>>(
        x, w1, NB * T_TOK, CIN, CIN, ident, bn1g, bn1b, bn1m, bn1v, Rp, C4);

    // [1..3] Res2Net scales (fused dw+pw+BN2, 8-token blocks, grid 576)
    for (int s = 1; s <= 3; s++) {
        const float* prev = (s == 1) ? nullptr : (Rp + (size_t)(s - 1) * NB * T_TOK * C4);
        dwpw8<<<(NB * T_TOK) / 8, 256>>>(
            ident, prev, dww, pww, bn2g, bn2b, bn2m, bn2v,
            Rp + (size_t)s * NB * T_TOK * C4, s);
    }

    // [4] fused Q/K/V projections -> fp16 (Q scaled by log2e)
    gemm_qkv<<<dim3(4, 144, 3), 256, GEMM_SMEM>>>(
        Rp, Wq, Wk, Wv, Qh, Kh, Vh);

    // [5] pure fp16 flash attention, 3-stage pipeline
    attn9<<<dim3(T_TOK / 128, NS * NB * NH), 256, AT_SMEM>>>(
        Qh, Kh, Vh, Op);

    // [6] output projection -> d_out
    gemm_mma<<<dim3(4, 36), 256, GEMM_SMEM>>>(
        Op, Wout, NB * T_TOK, CIN, 4 * CIN, out,
        nullptr, nullptr, nullptr, nullptr, nullptr, 0);
}